// round 12
// baseline (speedup 1.0000x reference)
#include <cuda_runtime.h>
#include <cstdint>

#define NN 100000
#define NE 800000
#define FIN 128
#define HID 64

static __device__ __constant__ float d_SCALE = 0.70710678118654752440f;
#define BN_EPS 1e-5f

// ---------------- scratch (device globals; no allocation) ----------------
__device__ float g_h0[NN * HID];   // fc output, later reused for h2
__device__ float g_t[NN * HID];    // (h @ w) * dego^-1/2
__device__ float g_agg[NN * HID];  // scatter-add accumulator
__device__ float g_h1[NN * HID];   // conv1 output
__device__ int   g_dego[NN];
__device__ int   g_degi[NN];
__device__ float g_sum[HID];
__device__ float g_ssq[HID];
__device__ float g_bna[HID];
__device__ float g_bnc[HID];

// packed fp32x2 FMA
#define FMA2(acc, a, b) \
    asm("fma.rn.f32x2 %0, %1, %2, %0;" : "+l"(acc) : "l"(a), "l"(b))
#define PACK_DUP(dst, fval) \
    asm("mov.b64 %0, {%1, %1};" : "=l"(dst) : "r"(__float_as_uint(fval)))
#define UNPACK2(lo, hi, p) \
    asm("mov.b64 {%0, %1}, %2;" : "=f"(lo), "=f"(hi) : "l"(p))

// ---------------- init: zero agg + degrees + BN accumulators ----------------
__global__ void k_init() {
    int i = blockIdx.x * blockDim.x + threadIdx.x;
    if (i < NN * (HID / 4))
        ((float4*)g_agg)[i] = make_float4(0.f, 0.f, 0.f, 0.f);
    if (i < NN) { g_dego[i] = 0; g_degi[i] = 0; }
    if (i < HID) { g_sum[i] = 0.f; g_ssq[i] = 0.f; }
}

// ---------------- degree counting ----------------
__global__ void k_degree(const int* __restrict__ src, const int* __restrict__ dst) {
    int e = blockIdx.x * blockDim.x + threadIdx.x;
    if (e < NE) {
        atomicAdd(&g_dego[src[e]], 1);
        atomicAdd(&g_degi[dst[e]], 1);
    }
}

// ======= packed-fp32 GEMM: C[N,64] = A[N,K] @ W[K,64], 256 thr =======
// KC=64 staging; lane -> 4 contiguous rows (A LDS.128 conflict-free),
// warp -> 8 cols (B broadcast). Needs carveout=100% for 4 blocks/SM.
// MODE 0: A = x,    C = g_h0, +bias            (K=128)
// MODE 1: A = g_h0, C = g_t,  * dego^-1/2      (K=64)
// MODE 2: A = g_h1, C = g_t,  * dego^-1/2      (K=64)
template <int MODE>
__global__ __launch_bounds__(256) void k_gemm(const float* __restrict__ Ain,
                                              const float* __restrict__ W,
                                              const float* __restrict__ bias) {
    constexpr int K = (MODE == 0) ? FIN : HID;
    constexpr int NCH = K / 64;

    __shared__ __align__(16) float At[64][128];   // 32 KB
    __shared__ __align__(16) float Ws[64][HID];   // 16 KB

    const float* A = (MODE == 0) ? Ain : ((MODE == 1) ? (const float*)g_h0
                                                      : (const float*)g_h1);
    float* C = (MODE == 0) ? (float*)g_h0 : (float*)g_t;

    const int t = threadIdx.x;
    const int lane = t & 31;
    const int warp = t >> 5;
    const int r0 = blockIdx.x * 128;
    const int tr = lane * 4;        // 4 consecutive rows -> A conflict-free
    const int tc = warp * 8;        // 8 cols per warp -> B broadcast

    unsigned long long acc[4][4];
#pragma unroll
    for (int i = 0; i < 4; i++)
#pragma unroll
        for (int j = 0; j < 4; j++) acc[i][j] = 0ULL;

    const int arow = t & 127;
    const int ahalf = t >> 7;       // which 32-float half of the 64-k chunk
    const int rload = min(r0 + arow, NN - 1);
    const float4* A4 = (const float4*)(A + (size_t)rload * K);
    const float4* W4 = (const float4*)W;

    float4 bb0, bb1;
    if (MODE == 0) {
        bb0 = __ldg((const float4*)&bias[tc]);
        bb1 = __ldg((const float4*)&bias[tc + 4]);
    }

    // prefetch chunk 0
    float4 va[8], vw[4];
#pragma unroll
    for (int j = 0; j < 8; j++) va[j] = A4[ahalf * 8 + j];
#pragma unroll
    for (int j = 0; j < 4; j++) {
        int idx = t + j * 256;
        vw[j] = W4[(idx >> 4) * (HID / 4) + (idx & 15)];
    }

#pragma unroll
    for (int ch = 0; ch < NCH; ch++) {
        if (ch > 0) __syncthreads();
        // store staged chunk to smem
#pragma unroll
        for (int j = 0; j < 8; j++) {
            At[ahalf * 32 + 4 * j + 0][arow] = va[j].x;
            At[ahalf * 32 + 4 * j + 1][arow] = va[j].y;
            At[ahalf * 32 + 4 * j + 2][arow] = va[j].z;
            At[ahalf * 32 + 4 * j + 3][arow] = va[j].w;
        }
#pragma unroll
        for (int j = 0; j < 4; j++) {
            int idx = t + j * 256;
            *((float4*)&Ws[idx >> 4][(idx & 15) * 4]) = vw[j];
        }
        __syncthreads();
        // prefetch next chunk while computing this one
        if (ch + 1 < NCH) {
#pragma unroll
            for (int j = 0; j < 8; j++) va[j] = A4[16 + ahalf * 8 + j];
#pragma unroll
            for (int j = 0; j < 4; j++) {
                int idx = t + j * 256;
                vw[j] = W4[(64 + (idx >> 4)) * (HID / 4) + (idx & 15)];
            }
        }
#pragma unroll 16
        for (int kk = 0; kk < 64; kk++) {
            unsigned long long bp[4];
            bp[0] = *(const unsigned long long*)&Ws[kk][tc + 0];
            bp[1] = *(const unsigned long long*)&Ws[kk][tc + 2];
            bp[2] = *(const unsigned long long*)&Ws[kk][tc + 4];
            bp[3] = *(const unsigned long long*)&Ws[kk][tc + 6];
            float4 a = *(const float4*)&At[kk][tr];
            float aa[4] = {a.x, a.y, a.z, a.w};
#pragma unroll
            for (int i = 0; i < 4; i++) {
                unsigned long long ad;
                PACK_DUP(ad, aa[i]);
#pragma unroll
                for (int j = 0; j < 4; j++) FMA2(acc[i][j], ad, bp[j]);
            }
        }
    }

#pragma unroll
    for (int i = 0; i < 4; i++) {
        int r = r0 + tr + i;
        if (r < NN) {
            float c0, c1, c2, c3, c4, c5, c6, c7;
            UNPACK2(c0, c1, acc[i][0]);
            UNPACK2(c2, c3, acc[i][1]);
            UNPACK2(c4, c5, acc[i][2]);
            UNPACK2(c6, c7, acc[i][3]);
            float4 o0, o1;
            if (MODE == 0) {
                o0.x = c0 + bb0.x; o0.y = c1 + bb0.y;
                o0.z = c2 + bb0.z; o0.w = c3 + bb0.w;
                o1.x = c4 + bb1.x; o1.y = c5 + bb1.y;
                o1.z = c6 + bb1.z; o1.w = c7 + bb1.w;
            } else {
                float sc = rsqrtf((float)max(g_dego[r], 1));
                o0.x = c0 * sc; o0.y = c1 * sc; o0.z = c2 * sc; o0.w = c3 * sc;
                o1.x = c4 * sc; o1.y = c5 * sc; o1.z = c6 * sc; o1.w = c7 * sc;
            }
            *((float4*)&C[(size_t)r * HID + tc]) = o0;
            *((float4*)&C[(size_t)r * HID + tc + 4]) = o1;
        }
    }
}

// ---------------- edge scatter: agg[dst] += t[src]  (16 threads / edge, v4 red) ----------------
__global__ void k_scatter(const int* __restrict__ src, const int* __restrict__ dst) {
    int idx = blockIdx.x * blockDim.x + threadIdx.x;
    if (idx >= NE * (HID / 4)) return;
    int e = idx >> 4;
    int c = idx & 15;
    int s = __ldg(&src[e]);
    int d = __ldg(&dst[e]);
    float4 v = ((const float4*)g_t)[s * 16 + c];
    float* p = &g_agg[d * HID + c * 4];
    asm volatile("red.global.add.v4.f32 [%0], {%1,%2,%3,%4};"
                 :: "l"(p), "f"(v.x), "f"(v.y), "f"(v.z), "f"(v.w)
                 : "memory");
}

// ------- combine1: h1 = (h0 + agg*nrmi + b1) * SCALE ; re-zero agg for conv2 -------
__global__ void k_combine1(const float* __restrict__ b1) {
    int idx = blockIdx.x * blockDim.x + threadIdx.x;
    if (idx >= NN * (HID / 4)) return;
    int row = idx >> 4;
    int c4 = idx & 15;
    float4 h = ((const float4*)g_h0)[idx];
    float4 a = ((const float4*)g_agg)[idx];
    float4 b = ((const float4*)b1)[c4];
    float nd = rsqrtf((float)max(g_degi[row], 1));
    float s = d_SCALE;
    float4 r;
    r.x = (h.x + a.x * nd + b.x) * s;
    r.y = (h.y + a.y * nd + b.y) * s;
    r.z = (h.z + a.z * nd + b.z) * s;
    r.w = (h.w + a.w * nd + b.w) * s;
    ((float4*)g_h1)[idx] = r;
    ((float4*)g_agg)[idx] = make_float4(0.f, 0.f, 0.f, 0.f);
}

// ------- combine2 + BN partial sums: h2 -> g_h0, accumulate sum/sumsq (float4) -------
__global__ __launch_bounds__(256) void k_combine2_bn(const float* __restrict__ b2) {
    const int T = gridDim.x * blockDim.x;       // multiple of 16
    int tg = blockIdx.x * blockDim.x + threadIdx.x;
    int c4 = tg & 15;                           // constant per thread
    float4 bb = ((const float4*)b2)[c4];
    float scl = d_SCALE;
    float4 s = make_float4(0.f, 0.f, 0.f, 0.f);
    float4 ss = make_float4(0.f, 0.f, 0.f, 0.f);
    for (int idx = tg; idx < NN * (HID / 4); idx += T) {
        int row = idx >> 4;
        float4 h = ((const float4*)g_h1)[idx];
        float4 a = ((const float4*)g_agg)[idx];
        float nd = rsqrtf((float)max(g_degi[row], 1));
        float4 v;
        v.x = (h.x + a.x * nd + bb.x) * scl;
        v.y = (h.y + a.y * nd + bb.y) * scl;
        v.z = (h.z + a.z * nd + bb.z) * scl;
        v.w = (h.w + a.w * nd + bb.w) * scl;
        ((float4*)g_h0)[idx] = v;
        s.x += v.x; s.y += v.y; s.z += v.z; s.w += v.w;
        ss.x += v.x * v.x; ss.y += v.y * v.y; ss.z += v.z * v.z; ss.w += v.w * v.w;
    }
    __shared__ float4 sh[256];
    sh[threadIdx.x] = s;
    __syncthreads();
    if (threadIdx.x < 16) {
        float4 tot = sh[threadIdx.x];
#pragma unroll
        for (int j = 1; j < 16; j++) {
            float4 o = sh[threadIdx.x + j * 16];
            tot.x += o.x; tot.y += o.y; tot.z += o.z; tot.w += o.w;
        }
        atomicAdd(&g_sum[threadIdx.x * 4 + 0], tot.x);
        atomicAdd(&g_sum[threadIdx.x * 4 + 1], tot.y);
        atomicAdd(&g_sum[threadIdx.x * 4 + 2], tot.z);
        atomicAdd(&g_sum[threadIdx.x * 4 + 3], tot.w);
    }
    __syncthreads();
    sh[threadIdx.x] = ss;
    __syncthreads();
    if (threadIdx.x < 16) {
        float4 tot = sh[threadIdx.x];
#pragma unroll
        for (int j = 1; j < 16; j++) {
            float4 o = sh[threadIdx.x + j * 16];
            tot.x += o.x; tot.y += o.y; tot.z += o.z; tot.w += o.w;
        }
        atomicAdd(&g_ssq[threadIdx.x * 4 + 0], tot.x);
        atomicAdd(&g_ssq[threadIdx.x * 4 + 1], tot.y);
        atomicAdd(&g_ssq[threadIdx.x * 4 + 2], tot.z);
        atomicAdd(&g_ssq[threadIdx.x * 4 + 3], tot.w);
    }
}

__global__ void k_bn_final(const float* __restrict__ gamma, const float* __restrict__ beta) {
    int f = threadIdx.x;
    float mu = g_sum[f] * (1.0f / NN);
    float var = g_ssq[f] * (1.0f / NN) - mu * mu;
    float a = gamma[f] * rsqrtf(var + BN_EPS);
    g_bna[f] = a;
    g_bnc[f] = beta[f] - mu * a;
}

__global__ void k_out(float* __restrict__ out) {
    int idx = blockIdx.x * blockDim.x + threadIdx.x;
    if (idx >= NN * (HID / 4)) return;
    int c4 = idx & 15;
    float4 h = ((const float4*)g_h0)[idx];
    float4 a = ((const float4*)g_bna)[c4];
    float4 c = ((const float4*)g_bnc)[c4];
    float4 r;
    r.x = h.x * a.x + c.x;
    r.y = h.y * a.y + c.y;
    r.z = h.z * a.z + c.z;
    r.w = h.w * a.w + c.w;
    ((float4*)out)[idx] = r;
}

// ---------------- launch ----------------
extern "C" void kernel_launch(void* const* d_in, const int* in_sizes, int n_in,
                              void* d_out, int out_size) {
    const int* src = (const int*)d_in[0];
    const int* dst = (const int*)d_in[1];
    const float* x = (const float*)d_in[2];
    const float* fc_w = (const float*)d_in[3];
    const float* fc_b = (const float*)d_in[4];
    const float* w1 = (const float*)d_in[5];
    const float* b1 = (const float*)d_in[6];
    const float* w2 = (const float*)d_in[7];
    const float* b2 = (const float*)d_in[8];
    const float* gamma = (const float*)d_in[9];
    const float* beta = (const float*)d_in[10];
    float* out = (float*)d_out;

    // carveout 100% -> 4 resident blocks/SM for the 48KB-smem GEMMs
    // (host attribute call: non-allocating, deterministic, capture-safe)
    cudaFuncSetAttribute(k_gemm<0>, cudaFuncAttributePreferredSharedMemoryCarveout, 100);
    cudaFuncSetAttribute(k_gemm<1>, cudaFuncAttributePreferredSharedMemoryCarveout, 100);
    cudaFuncSetAttribute(k_gemm<2>, cudaFuncAttributePreferredSharedMemoryCarveout, 100);

    const int nb_vec = (NN * (HID / 4) + 255) / 256;     // 6250
    const int nb_edge = (NE + 255) / 256;
    const int nb_scat = (NE * (HID / 4) + 255) / 256;    // 50000
    const int nb_gemm = (NN + 127) / 128;                // 782

    k_init<<<nb_vec, 256>>>();
    k_degree<<<nb_edge, 256>>>(src, dst);

    // h0 = x @ fc_w + fc_b
    k_gemm<0><<<nb_gemm, 256>>>(x, fc_w, fc_b);

    // conv1
    k_gemm<1><<<nb_gemm, 256>>>(nullptr, w1, nullptr);   // t = (h0@w1)*dego^-1/2
    k_scatter<<<nb_scat, 256>>>(src, dst);
    k_combine1<<<nb_vec, 256>>>(b1);                     // h1 + re-zero agg

    // conv2
    k_gemm<2><<<nb_gemm, 256>>>(nullptr, w2, nullptr);   // t = (h1@w2)*dego^-1/2
    k_scatter<<<nb_scat, 256>>>(src, dst);
    k_combine2_bn<<<256, 256>>>(b2);                     // h2 -> g_h0, BN partials

    k_bn_final<<<1, 64>>>(gamma, beta);
    k_out<<<nb_vec, 256>>>(out);
}